// round 15
// baseline (speedup 1.0000x reference)
#include <cuda_runtime.h>
#include <cuda_fp16.h>

typedef unsigned long long u64;

#define ATTRC    16
#define RADIALC  8
#define NMAX     10000
#define EMAX     100000

// ---------------------------------------------------------------------------
// Packed f32x2 helpers
// ---------------------------------------------------------------------------
__device__ __forceinline__ u64 fma2(u64 a, u64 b, u64 c) {
    u64 d; asm("fma.rn.f32x2 %0, %1, %2, %3;" : "=l"(d) : "l"(a), "l"(b), "l"(c)); return d;
}
__device__ __forceinline__ u64 splat2(float w) {
    u64 d; unsigned int b = __float_as_uint(w);
    asm("mov.b64 %0, {%1, %1};" : "=l"(d) : "r"(b)); return d;
}
__device__ __forceinline__ float2 unpk(u64 v) {
    unsigned int lo, hi; asm("mov.b64 {%0, %1}, %2;" : "=r"(lo), "=r"(hi) : "l"(v));
    return make_float2(__uint_as_float(lo), __uint_as_float(hi));
}

// ---------------------------------------------------------------------------
// Device scratch  (histogram arrays rely on static zero-init; scan re-zeroes
// them after reading so every graph replay sees zeros again)
// ---------------------------------------------------------------------------
__device__ __align__(16) float  g_WE[32768];          // [k=(r*32+u)][wp][4 blocks]
__device__ __align__(16) float  g_WS[32768];          // [k2=(u*16+v)][wp][2 paths]
__device__ __align__(16) __half g_Q[NMAX * 2048];     // Q[n][g][r][w]  (fp16, L2-resident)
__device__ __align__(16) __half g_ME[(size_t)EMAX * 128];  // messages, receiver-sorted
__device__ int g_cnt[NMAX];                           // sender histogram
__device__ int g_rcnt[NMAX];                          // receiver histogram
__device__ int g_startArr[NMAX + 1];                  // sender CSR
__device__ int g_cur[NMAX];
__device__ int g_rstart[NMAX + 1];                    // receiver CSR
__device__ int g_rcur[NMAX];
__device__ int g_eidx[EMAX];                          // edge ids grouped by sender
__device__ int g_rpos[EMAX];                          // per sender-slot: receiver-order dest
__device__ int g_work;                                // work-steal ticket

// ---------------------------------------------------------------------------
// Prep kernel: fold both weight sets + sender & receiver histograms.
//   c_edge = c_node = 1/128
// ---------------------------------------------------------------------------
__global__ void prep_kernel(const float* __restrict__ Wgen,
                            const float* __restrict__ L1s,
                            const float* __restrict__ L1v,
                            const float* __restrict__ WS0,
                            const float* __restrict__ WS1,
                            const float* __restrict__ L2s,
                            const float* __restrict__ L2v,
                            const int* __restrict__ edge_index,
                            int E)
{
    int i = blockIdx.x * blockDim.x + threadIdx.x;
    if (i < E) {
        atomicAdd(&g_cnt[edge_index[i]], 1);          // zeroed by scan
        atomicAdd(&g_rcnt[edge_index[E + i]], 1);     // zeroed by scan
    }

    if (i < 32768) {
        {   // fold edge weights
            int b   = i >> 13;
            int rem = i & 8191;
            int r   = rem >> 10;
            int u   = (rem >> 5) & 31;
            int wp  = rem & 31;
            const float* wg = Wgen + r * 4096 + b * 1024 + u * 32;
            const float* L  = (b == 1 || b == 2) ? L1v : L1s;
            float acc = 0.f;
#pragma unroll
            for (int w = 0; w < 32; w++) acc = fmaf(wg[w], L[w * 32 + wp], acc);
            float c = 0.0078125f;
            if (b == 3) c *= 0.57735026918962576f;   // fold 1/sqrt(3) into WD
            g_WE[(r * 32 + u) * 128 + wp * 4 + b] = acc * c;
        }
        {   // fold node weights
            int sb  = i >> 14;
            int rem = i & 16383;
            int uv  = rem >> 5;
            int wp  = rem & 31;
            const float* ws = (sb ? WS1 : WS0) + uv * 32;
            const float* L  = sb ? L2v : L2s;
            float acc = 0.f;
#pragma unroll
            for (int w = 0; w < 32; w++) acc = fmaf(ws[w], L[w * 32 + wp], acc);
            g_WS[uv * 64 + wp * 2 + sb] = acc * 0.0078125f;
        }
    }
}

// ---------------------------------------------------------------------------
// CSR: shfl-based exclusive scan, TWO passes (sender, receiver).
// Self-resets both histograms and g_work.
// ---------------------------------------------------------------------------
__global__ void scan_kernel(int N)
{
    __shared__ int wsum[32];
    __shared__ int wbase[32];
    __shared__ int carry;
    const int tid  = threadIdx.x;
    const int lane = tid & 31;
    const int wid  = tid >> 5;

    if (tid == 0) g_work = 0;

#pragma unroll 1
    for (int pass = 0; pass < 2; pass++) {
        int* cnt   = pass ? g_rcnt   : g_cnt;
        int* start = pass ? g_rstart : g_startArr;
        int* cur   = pass ? g_rcur   : g_cur;

        if (tid == 0) carry = 0;
        __syncthreads();

        for (int base = 0; base < N; base += 1024) {
            int i = base + tid;
            int v = 0;
            if (i < N) { v = cnt[i]; cnt[i] = 0; }   // read + reset for next replay
            int x = v;
#pragma unroll
            for (int off = 1; off < 32; off <<= 1) {
                int t = __shfl_up_sync(0xffffffffu, x, off);
                if (lane >= off) x += t;
            }
            if (lane == 31) wsum[wid] = x;
            __syncthreads();

            if (wid == 0) {
                int sv = wsum[lane];
                int y  = sv;
#pragma unroll
                for (int off = 1; off < 32; off <<= 1) {
                    int t = __shfl_up_sync(0xffffffffu, y, off);
                    if (lane >= off) y += t;
                }
                wbase[lane] = y - sv;
                if (lane == 31) wsum[0] = y;
            }
            __syncthreads();

            int c  = carry;
            int st = c + wbase[wid] + (x - v);
            if (i < N) { start[i] = st; cur[i] = st; }
            __syncthreads();
            if (tid == 0) carry = c + wsum[0];
            __syncthreads();
        }
        if (tid == 0) start[N] = carry;
        __syncthreads();
    }
}

// ===========================================================================
// Q kernel: Q[n][g][r][w] = sum_u Wg[r][u][w] * x[n][u]  (+ dual CSR scatter)
// 544 threads, 68-node tiles -> 148 tiles = 1 wave.  Q stored fp16.
// ===========================================================================
#define QTILE 68
#define QROW  68
#define QARR  2176
#define QW_OFF 0
#define QX_OFF 32768
#define Q_SMEM_FLOATS (QX_OFF + 4 * QARR)
#define Q_SMEM_BYTES  (Q_SMEM_FLOATS * 4)

__global__ void __launch_bounds__(544, 1)
q_kernel(const float* __restrict__ node_feats,
         const int* __restrict__ edge_index,
         int N, int E)
{
    extern __shared__ float s[];
    const int tid  = threadIdx.x;
    const int lane = tid & 31;
    const int eo   = tid >> 5;
    const int eb   = eo << 2;

    // dual CSR scatter (overlaps weight staging)
    for (int i = blockIdx.x * 544 + tid; i < E; i += gridDim.x * 544) {
        int snd = edge_index[i];
        int rcv = edge_index[E + i];
        int ps  = atomicAdd(&g_cur[snd], 1);
        g_eidx[ps] = i;
        int pr  = atomicAdd(&g_rcur[rcv], 1);
        g_rpos[ps] = pr;
    }

    for (int i = tid; i < 8192; i += 544)
        ((float4*)s)[i] = ((const float4*)g_WE)[i];

    const int ntiles = (N + QTILE - 1) / QTILE;

    for (int t = blockIdx.x; t < ntiles; t += gridDim.x) {
        const int n0 = t * QTILE;
        __syncthreads();

        for (int q = tid; q < QTILE * 128; q += 544) {
            int e = q >> 7, f = q & 127;
            int n = n0 + e;
            float v = (n < N) ? node_feats[(size_t)n * 128 + f] : 0.f;
            if (f < 32) {
                s[QX_OFF + f * QROW + e] = v;
            } else {
                int tt = f - 32;
                int uu = tt / 3;
                int ii = tt - uu * 3;
                s[QX_OFF + (1 + ii) * QARR + uu * QROW + e] = v;
            }
        }
        __syncthreads();

#pragma unroll 1
        for (int r = 0; r < 8; r++) {
            u64 acc[8][2];
#pragma unroll
            for (int g = 0; g < 8; g++) { acc[g][0] = 0ull; acc[g][1] = 0ull; }

            const int wbase2 = (r << 5) * 128 + lane * 4;
#pragma unroll 8
            for (int u = 0; u < 32; u++) {
                float4 wv = *(const float4*)&s[QW_OFF + wbase2 + u * 128];
                u64 wa = splat2(wv.x), wb = splat2(wv.y),
                    wc = splat2(wv.z), wd = splat2(wv.w);
                int xo = u * QROW + eb;
                ulonglong2 xs = *(const ulonglong2*)&s[QX_OFF + 0 * QARR + xo];
                ulonglong2 x0 = *(const ulonglong2*)&s[QX_OFF + 1 * QARR + xo];
                ulonglong2 x1 = *(const ulonglong2*)&s[QX_OFF + 2 * QARR + xo];
                ulonglong2 x2 = *(const ulonglong2*)&s[QX_OFF + 3 * QARR + xo];

                acc[0][0] = fma2(xs.x, wa, acc[0][0]); acc[0][1] = fma2(xs.y, wa, acc[0][1]);
                acc[1][0] = fma2(xs.x, wb, acc[1][0]); acc[1][1] = fma2(xs.y, wb, acc[1][1]);
                acc[2][0] = fma2(x0.x, wc, acc[2][0]); acc[2][1] = fma2(x0.y, wc, acc[2][1]);
                acc[3][0] = fma2(x1.x, wc, acc[3][0]); acc[3][1] = fma2(x1.y, wc, acc[3][1]);
                acc[4][0] = fma2(x2.x, wc, acc[4][0]); acc[4][1] = fma2(x2.y, wc, acc[4][1]);
                acc[5][0] = fma2(x0.x, wd, acc[5][0]); acc[5][1] = fma2(x0.y, wd, acc[5][1]);
                acc[6][0] = fma2(x1.x, wd, acc[6][0]); acc[6][1] = fma2(x1.y, wd, acc[6][1]);
                acc[7][0] = fma2(x2.x, wd, acc[7][0]); acc[7][1] = fma2(x2.y, wd, acc[7][1]);
            }

#pragma unroll
            for (int p = 0; p < 2; p++) {
#pragma unroll
                for (int h = 0; h < 2; h++) {
                    int n = n0 + eb + p * 2 + h;
                    if (n >= N) continue;
                    __half* qn = g_Q + (size_t)n * 2048 + r * 32 + lane;
#pragma unroll
                    for (int g = 0; g < 8; g++) {
                        float2 f2 = unpk(acc[g][p]);
                        qn[g * 256] = __float2half_rn(h ? f2.y : f2.x);
                    }
                }
            }
        }
    }
}

// ===========================================================================
// Edge kernel (CSR, work-stealing, NO atomics): warp grabs a sender ticket,
// Q row in registers, message stored fp16 at its receiver-CSR slot.
// ===========================================================================
__global__ void __launch_bounds__(512, 1)
edge_kernel(const float* __restrict__ edge_attrs,
            const float* __restrict__ edge_feats,
            int N)
{
    const int lane = threadIdx.x & 31;

    while (true) {
        int n = 0;
        if (lane == 0) n = atomicAdd(&g_work, 1);
        n = __shfl_sync(0xffffffffu, n, 0);
        if (n >= N) break;

        int s0 = g_startArr[n];
        int s1 = g_startArr[n + 1];
        if (s0 == s1) continue;

        const __half* Qn = g_Q + (size_t)n * 2048 + lane;
        float q[8][8];
#pragma unroll
        for (int g = 0; g < 8; g++)
#pragma unroll
            for (int r = 0; r < 8; r++)
                q[g][r] = __half2float(Qn[g * 256 + r * 32]);

        for (int c0 = s0; c0 < s1; c0 += 32) {
            int len = s1 - c0;
            if (len > 32) len = 32;

            // warp-wide prefetch of edge ids + destination slots
            int eV = 0, pV = 0;
            if (lane < len) {
                eV = __ldg(&g_eidx[c0 + lane]);
                pV = __ldg(&g_rpos[c0 + lane]);
            }

            for (int j = 0; j < len; j++) {
                int e   = __shfl_sync(0xffffffffu, eV, j);
                int pos = __shfl_sync(0xffffffffu, pV, j);

                float4 ea  = *(const float4*)&edge_attrs[(size_t)e * 4];
                float4 ef0 = *(const float4*)&edge_feats[(size_t)e * 8];
                float4 ef1 = *(const float4*)&edge_feats[(size_t)e * 8 + 4];

                float p[8];
#pragma unroll
                for (int g = 0; g < 8; g++) {
                    float a =        q[g][0] * ef0.x;
                    a = fmaf(q[g][1], ef0.y, a);
                    a = fmaf(q[g][2], ef0.z, a);
                    a = fmaf(q[g][3], ef0.w, a);
                    a = fmaf(q[g][4], ef1.x, a);
                    a = fmaf(q[g][5], ef1.y, a);
                    a = fmaf(q[g][6], ef1.z, a);
                    a = fmaf(q[g][7], ef1.w, a);
                    p[g] = a;
                }

                float ms  = fmaf(p[0], ea.x, fmaf(p[5], ea.y, fmaf(p[6], ea.z, p[7] * ea.w)));
                float mv0 = fmaf(p[1], ea.y, p[2] * ea.x);
                float mv1 = fmaf(p[1], ea.z, p[3] * ea.x);
                float mv2 = fmaf(p[1], ea.w, p[4] * ea.x);

                // pack 4 halves -> one 8B coalesced store per lane
                __half2 h0 = __floats2half2_rn(ms, mv0);
                __half2 h1 = __floats2half2_rn(mv1, mv2);
                unsigned int u0 = *reinterpret_cast<unsigned int*>(&h0);
                unsigned int u1 = *reinterpret_cast<unsigned int*>(&h1);
                u64 packed = (u64)u0 | ((u64)u1 << 32);
                *reinterpret_cast<u64*>(&g_ME[(size_t)pos * 128 + lane * 4]) = packed;
            }
        }
    }
}

// ===========================================================================
// Node kernel: 544 threads, 68-node tiles; gathers receiver-sorted messages
// (fp16) during staging; u-chunk(4) register caching of M for the skip GEMM.
// ===========================================================================
#define NROW  68
#define NARR  2176
#define NW_OFF  0
#define NMS_OFF 32768
#define NMV_OFF(i) (NMS_OFF + NARR * (1 + (i)))
#define NNA_OFF (NMS_OFF + NARR * 4)
#define NODE_SMEM_FLOATS (NNA_OFF + 16 * NROW)
#define NODE_SMEM_BYTES  (NODE_SMEM_FLOATS * 4)

__global__ void __launch_bounds__(544, 1)
node_kernel(const float* __restrict__ node_attrs,
            float* __restrict__ out,
            int N)
{
    extern __shared__ float s[];
    const int tid  = threadIdx.x;
    const int lane = tid & 31;
    const int eo   = tid >> 5;
    const int eb   = eo << 2;

    for (int i = tid; i < 8192; i += 544)
        ((float4*)s)[i] = ((const float4*)g_WS)[i];

    const int ntiles = (N + QTILE - 1) / QTILE;

    for (int t = blockIdx.x; t < ntiles; t += gridDim.x) {
        const int n0 = t * QTILE;
        __syncthreads();

        // stage M by gathering receiver-sorted fp16 messages (half2 granules)
        for (int q = tid; q < QTILE * 64; q += 544) {
            int e  = q >> 6;       // node within tile
            int f2 = q & 63;       // half2 index; f = 2*f2
            int n  = n0 + e;
            float2 accv = make_float2(0.f, 0.f);
            if (n < N) {
                int r0 = g_rstart[n], r1 = g_rstart[n + 1];
                for (int d = r0; d < r1; d++) {
                    __half2 h = *reinterpret_cast<const __half2*>(&g_ME[(size_t)d * 128 + f2 * 2]);
                    float2 v = __half22float2(h);
                    accv.x += v.x; accv.y += v.y;
                }
            }
            int f  = f2 * 2;
            int ln = f >> 2;
            if ((f & 3) == 0) {
                s[NMS_OFF    + ln * NROW + e] = accv.x;
                s[NMV_OFF(0) + ln * NROW + e] = accv.y;
            } else {
                s[NMV_OFF(1) + ln * NROW + e] = accv.x;
                s[NMV_OFF(2) + ln * NROW + e] = accv.y;
            }
        }
        for (int q = tid; q < QTILE * 16; q += 544) {
            int e = q >> 4, v = q & 15;
            int n = n0 + e;
            s[NNA_OFF + v * NROW + e] = (n < N) ? node_attrs[(size_t)n * 16 + v] : 0.f;
        }
        __syncthreads();

        u64 tot[8];
#pragma unroll
        for (int q = 0; q < 8; q++) tot[q] = 0ull;

#pragma unroll 1
        for (int uc = 0; uc < 32; uc += 4) {
            ulonglong2 mm[4][4];
#pragma unroll
            for (int j = 0; j < 4; j++) {
                int ao = (uc + j) * NROW + eb;
                mm[j][0] = *(const ulonglong2*)&s[NMS_OFF    + ao];
                mm[j][1] = *(const ulonglong2*)&s[NMV_OFF(0) + ao];
                mm[j][2] = *(const ulonglong2*)&s[NMV_OFF(1) + ao];
                mm[j][3] = *(const ulonglong2*)&s[NMV_OFF(2) + ao];
            }

#pragma unroll 1
            for (int v = 0; v < 16; v++) {
                u64 part[8];
#pragma unroll
                for (int q = 0; q < 8; q++) part[q] = 0ull;

#pragma unroll
                for (int j = 0; j < 4; j++) {
                    float2 wv = *(const float2*)&s[NW_OFF + ((uc + j) * 16 + v) * 64 + lane * 2];
                    u64 w0 = splat2(wv.x), w1 = splat2(wv.y);
                    part[0] = fma2(mm[j][0].x, w0, part[0]); part[1] = fma2(mm[j][0].y, w0, part[1]);
                    part[2] = fma2(mm[j][1].x, w1, part[2]); part[3] = fma2(mm[j][1].y, w1, part[3]);
                    part[4] = fma2(mm[j][2].x, w1, part[4]); part[5] = fma2(mm[j][2].y, w1, part[5]);
                    part[6] = fma2(mm[j][3].x, w1, part[6]); part[7] = fma2(mm[j][3].y, w1, part[7]);
                }

                ulonglong2 na = *(const ulonglong2*)&s[NNA_OFF + v * NROW + eb];
#pragma unroll
                for (int q = 0; q < 8; q += 2) {
                    tot[q]     = fma2(na.x, part[q],     tot[q]);
                    tot[q + 1] = fma2(na.y, part[q + 1], tot[q + 1]);
                }
            }
        }

#pragma unroll
        for (int p = 0; p < 2; p++) {
            float2 S  = unpk(tot[0 + p]);
            float2 V0 = unpk(tot[2 + p]);
            float2 V1 = unpk(tot[4 + p]);
            float2 V2 = unpk(tot[6 + p]);
#pragma unroll
            for (int h = 0; h < 2; h++) {
                int e = eb + 2 * p + h;
                int n = n0 + e;
                if (n >= N) continue;
                float* o = out + (size_t)n * 128;
                o[lane]              = s[NMS_OFF    + lane * NROW + e] + (h ? S.y  : S.x);
                o[32 + lane * 3 + 0] = s[NMV_OFF(0) + lane * NROW + e] + (h ? V0.y : V0.x);
                o[32 + lane * 3 + 1] = s[NMV_OFF(1) + lane * NROW + e] + (h ? V1.y : V1.x);
                o[32 + lane * 3 + 2] = s[NMV_OFF(2) + lane * NROW + e] + (h ? V2.y : V2.x);
            }
        }
    }
}

// ===========================================================================
// Launch
// ===========================================================================
extern "C" void kernel_launch(void* const* d_in, const int* in_sizes, int n_in,
                              void* d_out, int out_size)
{
    const float* node_attrs = (const float*)d_in[0];
    const float* node_feats = (const float*)d_in[1];
    const float* edge_attrs = (const float*)d_in[2];
    const float* edge_feats = (const float*)d_in[3];
    const int*   edge_index = (const int*)  d_in[4];
    const float* Wgen       = (const float*)d_in[5];
    const float* L1s        = (const float*)d_in[6];
    const float* L1v        = (const float*)d_in[7];
    const float* WS0        = (const float*)d_in[8];
    const float* WS1        = (const float*)d_in[9];
    const float* L2s        = (const float*)d_in[10];
    const float* L2v        = (const float*)d_in[11];
    float* out = (float*)d_out;

    const int N = in_sizes[0] / ATTRC;        // 10000
    const int E = in_sizes[3] / RADIALC;      // 100000
    const int ntiles = (N + QTILE - 1) / QTILE;   // 148

    cudaFuncSetAttribute(q_kernel,    cudaFuncAttributeMaxDynamicSharedMemorySize, Q_SMEM_BYTES);
    cudaFuncSetAttribute(node_kernel, cudaFuncAttributeMaxDynamicSharedMemorySize, NODE_SMEM_BYTES);

    prep_kernel<<<(E + 511) / 512, 512>>>(Wgen, L1s, L1v, WS0, WS1, L2s, L2v,
                                          edge_index, E);
    scan_kernel<<<1, 1024>>>(N);
    q_kernel<<<ntiles, 544, Q_SMEM_BYTES>>>(node_feats, edge_index, N, E);
    edge_kernel<<<148, 512>>>(edge_attrs, edge_feats, N);
    node_kernel<<<ntiles, 544, NODE_SMEM_BYTES>>>(node_attrs, out, N);
}

// round 16
// speedup vs baseline: 1.2215x; 1.2215x over previous
#include <cuda_runtime.h>
#include <cuda_fp16.h>

typedef unsigned long long u64;

#define ATTRC    16
#define RADIALC  8
#define NMAX     10000
#define EMAX     100000

// ---------------------------------------------------------------------------
// Packed f32x2 helpers
// ---------------------------------------------------------------------------
__device__ __forceinline__ u64 fma2(u64 a, u64 b, u64 c) {
    u64 d; asm("fma.rn.f32x2 %0, %1, %2, %3;" : "=l"(d) : "l"(a), "l"(b), "l"(c)); return d;
}
__device__ __forceinline__ u64 mul2(u64 a, u64 b) {
    u64 d; asm("mul.rn.f32x2 %0, %1, %2;" : "=l"(d) : "l"(a), "l"(b)); return d;
}
__device__ __forceinline__ u64 splat2(float w) {
    u64 d; unsigned int b = __float_as_uint(w);
    asm("mov.b64 %0, {%1, %1};" : "=l"(d) : "r"(b)); return d;
}
__device__ __forceinline__ u64 pack2(float lo, float hi) {
    u64 d; asm("mov.b64 %0, {%1, %2};" : "=l"(d) : "f"(lo), "f"(hi)); return d;
}
__device__ __forceinline__ float2 unpk(u64 v) {
    unsigned int lo, hi; asm("mov.b64 {%0, %1}, %2;" : "=r"(lo), "=r"(hi) : "l"(v));
    return make_float2(__uint_as_float(lo), __uint_as_float(hi));
}
__device__ __forceinline__ void red_v4(float* p, float a, float b, float c, float d) {
    asm volatile("red.global.add.v4.f32 [%0], {%1, %2, %3, %4};"
                 :: "l"(p), "f"(a), "f"(b), "f"(c), "f"(d) : "memory");
}

// ---------------------------------------------------------------------------
// Device scratch  (g_cnt relies on static zero-init; scan re-zeroes it after
// reading so every graph replay sees zeros again)
// ---------------------------------------------------------------------------
__device__ __align__(16) float  g_WE[32768];          // [k=(r*32+u)][wp][4 blocks]
__device__ __align__(16) float  g_WS[32768];          // [k2=(u*16+v)][wp][2 paths]
__device__ __align__(16) float  g_M[NMAX * 128];      // messages [n][lane][4]=(ms,mv0,mv1,mv2)
__device__ __align__(16) __half g_Q[NMAX * 2048];     // Q[n][g][r][w]  (fp16, L2-resident)
__device__ int g_cnt[NMAX];
__device__ int g_startArr[NMAX + 1];
__device__ int g_cur[NMAX];
__device__ int g_eidx[EMAX];
__device__ int g_work;                                // work-steal ticket

// ---------------------------------------------------------------------------
// Prep kernel: fold both weight sets + zero M + sender histogram, one launch.
//   c_edge = c_node = 1/128
// ---------------------------------------------------------------------------
__global__ void prep_kernel(const float* __restrict__ Wgen,
                            const float* __restrict__ L1s,
                            const float* __restrict__ L1v,
                            const float* __restrict__ WS0,
                            const float* __restrict__ WS1,
                            const float* __restrict__ L2s,
                            const float* __restrict__ L2v,
                            const int* __restrict__ edge_index,
                            int nM, int E)
{
    int i = blockIdx.x * blockDim.x + threadIdx.x;
    if (i < nM) g_M[i] = 0.f;
    if (i < E)  atomicAdd(&g_cnt[edge_index[i]], 1);   // g_cnt zeroed by scan

    if (i < 32768) {
        {   // fold edge weights
            int b   = i >> 13;
            int rem = i & 8191;
            int r   = rem >> 10;
            int u   = (rem >> 5) & 31;
            int wp  = rem & 31;
            const float* wg = Wgen + r * 4096 + b * 1024 + u * 32;
            const float* L  = (b == 1 || b == 2) ? L1v : L1s;
            float acc = 0.f;
#pragma unroll
            for (int w = 0; w < 32; w++) acc = fmaf(wg[w], L[w * 32 + wp], acc);
            float c = 0.0078125f;
            if (b == 3) c *= 0.57735026918962576f;   // fold 1/sqrt(3) into WD
            g_WE[(r * 32 + u) * 128 + wp * 4 + b] = acc * c;
        }
        {   // fold node weights
            int sb  = i >> 14;
            int rem = i & 16383;
            int uv  = rem >> 5;
            int wp  = rem & 31;
            const float* ws = (sb ? WS1 : WS0) + uv * 32;
            const float* L  = sb ? L2v : L2s;
            float acc = 0.f;
#pragma unroll
            for (int w = 0; w < 32; w++) acc = fmaf(ws[w], L[w * 32 + wp], acc);
            g_WS[uv * 64 + wp * 2 + sb] = acc * 0.0078125f;
        }
    }
}

// ---------------------------------------------------------------------------
// CSR: shfl-based exclusive scan; self-resets g_cnt and g_work.
// ---------------------------------------------------------------------------
__global__ void scan_kernel(int N)
{
    __shared__ int wsum[32];
    __shared__ int wbase[32];
    __shared__ int carry;
    const int tid  = threadIdx.x;
    const int lane = tid & 31;
    const int wid  = tid >> 5;

    if (tid == 0) { carry = 0; g_work = 0; }
    __syncthreads();

    for (int base = 0; base < N; base += 1024) {
        int i = base + tid;
        int v = 0;
        if (i < N) { v = g_cnt[i]; g_cnt[i] = 0; }   // read + reset for next replay
        int x = v;
#pragma unroll
        for (int off = 1; off < 32; off <<= 1) {
            int t = __shfl_up_sync(0xffffffffu, x, off);
            if (lane >= off) x += t;
        }
        if (lane == 31) wsum[wid] = x;
        __syncthreads();

        if (wid == 0) {
            int sv = wsum[lane];
            int y  = sv;
#pragma unroll
            for (int off = 1; off < 32; off <<= 1) {
                int t = __shfl_up_sync(0xffffffffu, y, off);
                if (lane >= off) y += t;
            }
            wbase[lane] = y - sv;
            if (lane == 31) wsum[0] = y;
        }
        __syncthreads();

        int c  = carry;
        int st = c + wbase[wid] + (x - v);
        if (i < N) { g_startArr[i] = st; g_cur[i] = st; }
        __syncthreads();
        if (tid == 0) carry = c + wsum[0];
        __syncthreads();
    }
    if (tid == 0) g_startArr[N] = carry;
}

// ===========================================================================
// Q kernel: Q[n][g][r][w] = sum_u Wg[r][u][w] * x[n][u]  (+ CSR scatter)
// 544 threads, 68-node tiles -> 148 tiles = 1 wave.  Q stored fp16.
// ===========================================================================
#define QTILE 68
#define QROW  68
#define QARR  2176
#define QW_OFF 0
#define QX_OFF 32768
#define Q_SMEM_FLOATS (QX_OFF + 4 * QARR)
#define Q_SMEM_BYTES  (Q_SMEM_FLOATS * 4)

__global__ void __launch_bounds__(544, 1)
q_kernel(const float* __restrict__ node_feats,
         const int* __restrict__ edge_index,
         int N, int E)
{
    extern __shared__ float s[];
    const int tid  = threadIdx.x;
    const int lane = tid & 31;
    const int eo   = tid >> 5;
    const int eb   = eo << 2;

    // CSR scatter (overlaps weight staging)
    for (int i = blockIdx.x * 544 + tid; i < E; i += gridDim.x * 544) {
        int pos = atomicAdd(&g_cur[edge_index[i]], 1);
        g_eidx[pos] = i;
    }

    for (int i = tid; i < 8192; i += 544)
        ((float4*)s)[i] = ((const float4*)g_WE)[i];

    const int ntiles = (N + QTILE - 1) / QTILE;

    for (int t = blockIdx.x; t < ntiles; t += gridDim.x) {
        const int n0 = t * QTILE;
        __syncthreads();

        for (int q = tid; q < QTILE * 128; q += 544) {
            int e = q >> 7, f = q & 127;
            int n = n0 + e;
            float v = (n < N) ? node_feats[(size_t)n * 128 + f] : 0.f;
            if (f < 32) {
                s[QX_OFF + f * QROW + e] = v;
            } else {
                int tt = f - 32;
                int uu = tt / 3;
                int ii = tt - uu * 3;
                s[QX_OFF + (1 + ii) * QARR + uu * QROW + e] = v;
            }
        }
        __syncthreads();

#pragma unroll 1
        for (int r = 0; r < 8; r++) {
            u64 acc[8][2];
#pragma unroll
            for (int g = 0; g < 8; g++) { acc[g][0] = 0ull; acc[g][1] = 0ull; }

            const int wbase2 = (r << 5) * 128 + lane * 4;
#pragma unroll 8
            for (int u = 0; u < 32; u++) {
                float4 wv = *(const float4*)&s[QW_OFF + wbase2 + u * 128];
                u64 wa = splat2(wv.x), wb = splat2(wv.y),
                    wc = splat2(wv.z), wd = splat2(wv.w);
                int xo = u * QROW + eb;
                ulonglong2 xs = *(const ulonglong2*)&s[QX_OFF + 0 * QARR + xo];
                ulonglong2 x0 = *(const ulonglong2*)&s[QX_OFF + 1 * QARR + xo];
                ulonglong2 x1 = *(const ulonglong2*)&s[QX_OFF + 2 * QARR + xo];
                ulonglong2 x2 = *(const ulonglong2*)&s[QX_OFF + 3 * QARR + xo];

                acc[0][0] = fma2(xs.x, wa, acc[0][0]); acc[0][1] = fma2(xs.y, wa, acc[0][1]);
                acc[1][0] = fma2(xs.x, wb, acc[1][0]); acc[1][1] = fma2(xs.y, wb, acc[1][1]);
                acc[2][0] = fma2(x0.x, wc, acc[2][0]); acc[2][1] = fma2(x0.y, wc, acc[2][1]);
                acc[3][0] = fma2(x1.x, wc, acc[3][0]); acc[3][1] = fma2(x1.y, wc, acc[3][1]);
                acc[4][0] = fma2(x2.x, wc, acc[4][0]); acc[4][1] = fma2(x2.y, wc, acc[4][1]);
                acc[5][0] = fma2(x0.x, wd, acc[5][0]); acc[5][1] = fma2(x0.y, wd, acc[5][1]);
                acc[6][0] = fma2(x1.x, wd, acc[6][0]); acc[6][1] = fma2(x1.y, wd, acc[6][1]);
                acc[7][0] = fma2(x2.x, wd, acc[7][0]); acc[7][1] = fma2(x2.y, wd, acc[7][1]);
            }

#pragma unroll
            for (int p = 0; p < 2; p++) {
#pragma unroll
                for (int h = 0; h < 2; h++) {
                    int n = n0 + eb + p * 2 + h;
                    if (n >= N) continue;
                    __half* qn = g_Q + (size_t)n * 2048 + r * 32 + lane;
#pragma unroll
                    for (int g = 0; g < 8; g++) {
                        float2 f2 = unpk(acc[g][p]);
                        qn[g * 256] = __float2half_rn(h ? f2.y : f2.x);
                    }
                }
            }
        }
    }
}

// ===========================================================================
// Edge kernel (CSR, work-stealing, f32x2-packed compute):
//   - warp grabs a sender ticket; Q row converted once into packed pairs
//     qp[p][r] = (q[2p][r], q[2p+1][r])
//   - per edge: 8 ef splats + 32 fma2 replace 64 scalar FMA
//   - v4 red scatter into g_M
// ===========================================================================
__global__ void __launch_bounds__(512, 1)
edge_kernel(const float* __restrict__ edge_attrs,
            const float* __restrict__ edge_feats,
            const int*   __restrict__ edge_index,
            int E, int N)
{
    const int lane = threadIdx.x & 31;

    while (true) {
        int n = 0;
        if (lane == 0) n = atomicAdd(&g_work, 1);
        n = __shfl_sync(0xffffffffu, n, 0);
        if (n >= N) break;

        int s0 = g_startArr[n];
        int s1 = g_startArr[n + 1];
        if (s0 == s1) continue;

        // load + pack Q row: qp[p][r] holds (p_g, p_{g+1}) lanes for g=2p
        const __half* Qn = g_Q + (size_t)n * 2048 + lane;
        u64 qp[4][8];
#pragma unroll
        for (int p = 0; p < 4; p++)
#pragma unroll
            for (int r = 0; r < 8; r++) {
                float a = __half2float(Qn[(2 * p)     * 256 + r * 32]);
                float b = __half2float(Qn[(2 * p + 1) * 256 + r * 32]);
                qp[p][r] = pack2(a, b);
            }

        for (int c0 = s0; c0 < s1; c0 += 32) {
            int len = s1 - c0;
            if (len > 32) len = 32;

            // warp-wide prefetch of edge ids + receivers for this chunk
            int eV = 0, rV = 0;
            if (lane < len) {
                eV = __ldg(&g_eidx[c0 + lane]);
                rV = __ldg(&edge_index[E + eV]);
            }

            for (int j = 0; j < len; j++) {
                int e   = __shfl_sync(0xffffffffu, eV, j);
                int rcv = __shfl_sync(0xffffffffu, rV, j);

                float4 ea  = *(const float4*)&edge_attrs[(size_t)e * 4];
                float4 ef0 = *(const float4*)&edge_feats[(size_t)e * 8];
                float4 ef1 = *(const float4*)&edge_feats[(size_t)e * 8 + 4];

                u64 s0v = splat2(ef0.x), s1v = splat2(ef0.y),
                    s2v = splat2(ef0.z), s3v = splat2(ef0.w),
                    s4v = splat2(ef1.x), s5v = splat2(ef1.y),
                    s6v = splat2(ef1.z), s7v = splat2(ef1.w);

                u64 acc[4];
#pragma unroll
                for (int p = 0; p < 4; p++) {
                    u64 a = mul2(qp[p][0], s0v);
                    a = fma2(qp[p][1], s1v, a);
                    a = fma2(qp[p][2], s2v, a);
                    a = fma2(qp[p][3], s3v, a);
                    a = fma2(qp[p][4], s4v, a);
                    a = fma2(qp[p][5], s5v, a);
                    a = fma2(qp[p][6], s6v, a);
                    a = fma2(qp[p][7], s7v, a);
                    acc[p] = a;
                }

                float2 P01 = unpk(acc[0]);   // p0, p1
                float2 P23 = unpk(acc[1]);   // p2, p3
                float2 P45 = unpk(acc[2]);   // p4, p5
                float2 P67 = unpk(acc[3]);   // p6, p7

                float ms  = fmaf(P01.x, ea.x,
                             fmaf(P45.y, ea.y, fmaf(P67.x, ea.z, P67.y * ea.w)));
                float mv0 = fmaf(P01.y, ea.y, P23.x * ea.x);
                float mv1 = fmaf(P01.y, ea.z, P23.y * ea.x);
                float mv2 = fmaf(P01.y, ea.w, P45.x * ea.x);

                red_v4(g_M + (size_t)rcv * 128 + lane * 4, ms, mv0, mv1, mv2);
            }
        }
    }
}

// ===========================================================================
// Node kernel: 544 threads, 68-node tiles, u-chunk(4) register caching of M.
// ===========================================================================
#define NROW  68
#define NARR  2176
#define NW_OFF  0
#define NMS_OFF 32768
#define NMV_OFF(i) (NMS_OFF + NARR * (1 + (i)))
#define NNA_OFF (NMS_OFF + NARR * 4)
#define NODE_SMEM_FLOATS (NNA_OFF + 16 * NROW)
#define NODE_SMEM_BYTES  (NODE_SMEM_FLOATS * 4)

__global__ void __launch_bounds__(544, 1)
node_kernel(const float* __restrict__ node_attrs,
            float* __restrict__ out,
            int N)
{
    extern __shared__ float s[];
    const int tid  = threadIdx.x;
    const int lane = tid & 31;
    const int eo   = tid >> 5;
    const int eb   = eo << 2;

    for (int i = tid; i < 8192; i += 544)
        ((float4*)s)[i] = ((const float4*)g_WS)[i];

    const int ntiles = (N + QTILE - 1) / QTILE;

    for (int t = blockIdx.x; t < ntiles; t += gridDim.x) {
        const int n0 = t * QTILE;
        __syncthreads();

        // stage M ([n][ln][4] = ms,mv0,mv1,mv2)
        for (int q = tid; q < QTILE * 128; q += 544) {
            int e = q >> 7, f = q & 127;
            int n = n0 + e;
            float v = (n < N) ? g_M[(size_t)n * 128 + f] : 0.f;
            int ln = f >> 2, c = f & 3;
            if (c == 0) s[NMS_OFF + ln * NROW + e] = v;
            else        s[NMV_OFF(c - 1) + ln * NROW + e] = v;
        }
        for (int q = tid; q < QTILE * 16; q += 544) {
            int e = q >> 4, v = q & 15;
            int n = n0 + e;
            s[NNA_OFF + v * NROW + e] = (n < N) ? node_attrs[(size_t)n * 16 + v] : 0.f;
        }
        __syncthreads();

        u64 tot[8];
#pragma unroll
        for (int q = 0; q < 8; q++) tot[q] = 0ull;

#pragma unroll 1
        for (int uc = 0; uc < 32; uc += 4) {
            ulonglong2 mm[4][4];
#pragma unroll
            for (int j = 0; j < 4; j++) {
                int ao = (uc + j) * NROW + eb;
                mm[j][0] = *(const ulonglong2*)&s[NMS_OFF    + ao];
                mm[j][1] = *(const ulonglong2*)&s[NMV_OFF(0) + ao];
                mm[j][2] = *(const ulonglong2*)&s[NMV_OFF(1) + ao];
                mm[j][3] = *(const ulonglong2*)&s[NMV_OFF(2) + ao];
            }

#pragma unroll 1
            for (int v = 0; v < 16; v++) {
                u64 part[8];
#pragma unroll
                for (int q = 0; q < 8; q++) part[q] = 0ull;

#pragma unroll
                for (int j = 0; j < 4; j++) {
                    float2 wv = *(const float2*)&s[NW_OFF + ((uc + j) * 16 + v) * 64 + lane * 2];
                    u64 w0 = splat2(wv.x), w1 = splat2(wv.y);
                    part[0] = fma2(mm[j][0].x, w0, part[0]); part[1] = fma2(mm[j][0].y, w0, part[1]);
                    part[2] = fma2(mm[j][1].x, w1, part[2]); part[3] = fma2(mm[j][1].y, w1, part[3]);
                    part[4] = fma2(mm[j][2].x, w1, part[4]); part[5] = fma2(mm[j][2].y, w1, part[5]);
                    part[6] = fma2(mm[j][3].x, w1, part[6]); part[7] = fma2(mm[j][3].y, w1, part[7]);
                }

                ulonglong2 na = *(const ulonglong2*)&s[NNA_OFF + v * NROW + eb];
#pragma unroll
                for (int q = 0; q < 8; q += 2) {
                    tot[q]     = fma2(na.x, part[q],     tot[q]);
                    tot[q + 1] = fma2(na.y, part[q + 1], tot[q + 1]);
                }
            }
        }

#pragma unroll
        for (int p = 0; p < 2; p++) {
            float2 S  = unpk(tot[0 + p]);
            float2 V0 = unpk(tot[2 + p]);
            float2 V1 = unpk(tot[4 + p]);
            float2 V2 = unpk(tot[6 + p]);
#pragma unroll
            for (int h = 0; h < 2; h++) {
                int e = eb + 2 * p + h;
                int n = n0 + e;
                if (n >= N) continue;
                float* o = out + (size_t)n * 128;
                o[lane]              = s[NMS_OFF    + lane * NROW + e] + (h ? S.y  : S.x);
                o[32 + lane * 3 + 0] = s[NMV_OFF(0) + lane * NROW + e] + (h ? V0.y : V0.x);
                o[32 + lane * 3 + 1] = s[NMV_OFF(1) + lane * NROW + e] + (h ? V1.y : V1.x);
                o[32 + lane * 3 + 2] = s[NMV_OFF(2) + lane * NROW + e] + (h ? V2.y : V2.x);
            }
        }
    }
}

// ===========================================================================
// Launch
// ===========================================================================
extern "C" void kernel_launch(void* const* d_in, const int* in_sizes, int n_in,
                              void* d_out, int out_size)
{
    const float* node_attrs = (const float*)d_in[0];
    const float* node_feats = (const float*)d_in[1];
    const float* edge_attrs = (const float*)d_in[2];
    const float* edge_feats = (const float*)d_in[3];
    const int*   edge_index = (const int*)  d_in[4];
    const float* Wgen       = (const float*)d_in[5];
    const float* L1s        = (const float*)d_in[6];
    const float* L1v        = (const float*)d_in[7];
    const float* WS0        = (const float*)d_in[8];
    const float* WS1        = (const float*)d_in[9];
    const float* L2s        = (const float*)d_in[10];
    const float* L2v        = (const float*)d_in[11];
    float* out = (float*)d_out;

    const int N = in_sizes[0] / ATTRC;        // 10000
    const int E = in_sizes[3] / RADIALC;      // 100000
    const int ntiles = (N + QTILE - 1) / QTILE;   // 148

    cudaFuncSetAttribute(q_kernel,    cudaFuncAttributeMaxDynamicSharedMemorySize, Q_SMEM_BYTES);
    cudaFuncSetAttribute(node_kernel, cudaFuncAttributeMaxDynamicSharedMemorySize, NODE_SMEM_BYTES);

    prep_kernel<<<(N * 128 + 511) / 512, 512>>>(Wgen, L1s, L1v, WS0, WS1, L2s, L2v,
                                                edge_index, N * 128, E);
    scan_kernel<<<1, 1024>>>(N);
    q_kernel<<<ntiles, 544, Q_SMEM_BYTES>>>(node_feats, edge_index, N, E);
    edge_kernel<<<148, 512>>>(edge_attrs, edge_feats, edge_index, E, N);
    node_kernel<<<ntiles, 544, NODE_SMEM_BYTES>>>(node_attrs, out, N);
}